// round 9
// baseline (speedup 1.0000x reference)
#include <cuda_runtime.h>
#include <math.h>

#define B_ 16
#define L_ 200
#define H_ 128
#define NH_ 4
#define HS_ 32
#define T_ 257
#define BT_ (B_*L_)
#define QT 8                    // queries per attention block
#define NEGF (-4294967295.0f)   // -2^32+1 -> rounds to -2^32 in fp32 (same as JAX fp32)
#define SQRT_H 11.313708498984761f
#define SCALE 0.17677669529663689f  // 1/sqrt(32)

// packed f32x2 helpers (ptxas never auto-fuses; PTX-only path)
#define PACK2(dst, a, b)  asm("mov.b64 %0, {%1, %2};" : "=l"(dst) : "f"(a), "f"(b))
#define UNPACK2(lo, hi, s) asm("mov.b64 {%0, %1}, %2;" : "=f"(lo), "=f"(hi) : "l"(s))
#define FMA2(d, x, w)     asm("fma.rn.f32x2 %0, %1, %2, %0;" : "+l"(d) : "l"(x), "l"(w))

typedef unsigned long long u64;

// -------- scratch (device globals; no allocation) --------
__device__ float g_seqs [BT_*H_];
__device__ float g_qin  [BT_*H_];
__device__ float g_q    [BT_*H_];
__device__ float g_k    [BT_*H_];
__device__ float g_v    [BT_*H_];
__device__ float g_attn [BT_*H_];

// ======== GEMM building blocks: 16 rows x 128 cols, f32x2-packed row pairs ========
// 256 threads: j = tid&127 (output col), half = tid>>7 owns rows 8*half..+7.
#define GROWS 16
#define WPAD 36   // Ws stride (144B): conflict-free LDS.128/STS.128
#define XTS  20   // Xt stride (80B): 16B-multiple -> aligned ulonglong2 reads
#define SSTR 132  // staging row stride in floats (528B, 16B-multiple)

// gather 16 embedded rows into stage: stage[r][k] = (id? emb[id][k]*sqrt(H) : 0)
__device__ __forceinline__ void embed_to_stage(
    const int* __restrict__ ids, const float* __restrict__ emb,
    int row0, int tid, float* stage, int* ids_sm) {
    if (tid < GROWS) ids_sm[tid] = ids[row0 + tid];
    __syncthreads();
    for (int idx = tid; idx < GROWS * (H_ / 4); idx += 256) {
        int r = idx >> 5, k4 = idx & 31;           // H_/4 == 32
        int id = ids_sm[r];
        float4 v = make_float4(0.0f, 0.0f, 0.0f, 0.0f);
        if (id != 0) {
            v = ((const float4*)(emb + id * H_))[k4];
            v.x *= SQRT_H; v.y *= SQRT_H; v.z *= SQRT_H; v.w *= SQRT_H;
        }
        *(float4*)&stage[r * SSTR + 4 * k4] = v;
    }
}

// warp-per-2-rows LN of X(+Res) from GLOBAL -> staging buffer, optional global out
__device__ __forceinline__ void ln_rows_to_stage(
    const float* __restrict__ X, const float* __restrict__ Res,
    const float* __restrict__ g, const float* __restrict__ b,
    float* __restrict__ gout, int row0, int tid, float* stage) {
    int w = tid >> 5, lane = tid & 31;
    float4 gv = ((const float4*)g)[lane];
    float4 bv = ((const float4*)b)[lane];
    #pragma unroll
    for (int ii = 0; ii < 2; ii++) {
        int r = 2 * w + ii;
        int row = row0 + r;
        float4 xv = ((const float4*)(X + row * H_))[lane];
        if (Res) {
            float4 rv = ((const float4*)(Res + row * H_))[lane];
            xv.x += rv.x; xv.y += rv.y; xv.z += rv.z; xv.w += rv.w;
        }
        float s  = xv.x + xv.y + xv.z + xv.w;
        float s2 = xv.x * xv.x + xv.y * xv.y + xv.z * xv.z + xv.w * xv.w;
        #pragma unroll
        for (int o = 16; o; o >>= 1) {
            s  += __shfl_xor_sync(0xffffffffu, s,  o);
            s2 += __shfl_xor_sync(0xffffffffu, s2, o);
        }
        float mean = s * (1.0f / H_);
        float var  = s2 * (1.0f / H_) - mean * mean;
        float rs = rsqrtf(var + 1e-8f);
        float4 nv;
        nv.x = (xv.x - mean) * rs * gv.x + bv.x;
        nv.y = (xv.y - mean) * rs * gv.y + bv.y;
        nv.z = (xv.z - mean) * rs * gv.z + bv.z;
        nv.w = (xv.w - mean) * rs * gv.w + bv.w;
        if (gout) ((float4*)(gout + row * H_))[lane] = nv;
        *(float4*)&stage[r * SSTR + 4 * lane] = nv;
    }
}

// warp-per-2-rows LN IN PLACE on the staged rows, optional global out
__device__ __forceinline__ void ln_stage_inplace(
    const float* __restrict__ g, const float* __restrict__ b,
    float* __restrict__ gout, int row0, int tid, float* stage) {
    int w = tid >> 5, lane = tid & 31;
    float4 gv = ((const float4*)g)[lane];
    float4 bv = ((const float4*)b)[lane];
    #pragma unroll
    for (int ii = 0; ii < 2; ii++) {
        int r = 2 * w + ii;
        float4 xv = *(const float4*)&stage[r * SSTR + 4 * lane];
        float s  = xv.x + xv.y + xv.z + xv.w;
        float s2 = xv.x * xv.x + xv.y * xv.y + xv.z * xv.z + xv.w * xv.w;
        #pragma unroll
        for (int o = 16; o; o >>= 1) {
            s  += __shfl_xor_sync(0xffffffffu, s,  o);
            s2 += __shfl_xor_sync(0xffffffffu, s2, o);
        }
        float mean = s * (1.0f / H_);
        float var  = s2 * (1.0f / H_) - mean * mean;
        float rs = rsqrtf(var + 1e-8f);
        float4 nv;
        nv.x = (xv.x - mean) * rs * gv.x + bv.x;
        nv.y = (xv.y - mean) * rs * gv.y + bv.y;
        nv.z = (xv.z - mean) * rs * gv.z + bv.z;
        nv.w = (xv.w - mean) * rs * gv.w + bv.w;
        if (gout) ((float4*)(gout + (row0 + r) * H_))[lane] = nv;
        *(float4*)&stage[r * SSTR + 4 * lane] = nv;
    }
}

// cooperative transposed fill Xt[k][r] <- stage[r][k]
__device__ __forceinline__ void stage_to_xt(const float* stage, int tid, float (*Xt)[XTS]) {
    for (int idx = tid; idx < GROWS * H_; idx += 256) {
        int r = idx >> 7, k = idx & 127;
        Xt[k][r] = stage[r * SSTR + k];
    }
}

// plain transposed fill from global row-major X
__device__ __forceinline__ void global_to_xt(const float* __restrict__ X, int row0,
                                             int tid, float (*Xt)[XTS]) {
    for (int idx = tid; idx < GROWS * H_; idx += 256) {
        int r = idx >> 7, k = idx & 127;
        Xt[k][r] = X[row0 * H_ + idx];
    }
}

// main loop: acc(4 x f32x2 row-pairs) = bias + Xt^T row-block . W[j]
// chunk-top __syncthreads also orders the caller's preceding Xt/stage writes.
__device__ __forceinline__ void gemm_mainloop(
    const float* __restrict__ W, float bj, int tid, int j, int half,
    const float (*Xt)[XTS], float (*Ws)[WPAD], u64 acc[4]) {
    #pragma unroll
    for (int p = 0; p < 4; p++) PACK2(acc[p], bj, bj);
    for (int kc = 0; kc < H_; kc += 32) {
        __syncthreads();
        for (int idx = tid; idx < 128 * 8; idx += 256) {
            int jj = idx >> 3, f4 = idx & 7;
            *(float4*)&Ws[jj][f4 * 4] = *(const float4*)&W[jj * H_ + kc + f4 * 4];
        }
        __syncthreads();
        #pragma unroll
        for (int k4 = 0; k4 < 8; k4++) {
            float4 wv = *(const float4*)&Ws[j][k4 * 4];
            u64 wp[4];
            PACK2(wp[0], wv.x, wv.x);
            PACK2(wp[1], wv.y, wv.y);
            PACK2(wp[2], wv.z, wv.z);
            PACK2(wp[3], wv.w, wv.w);
            #pragma unroll
            for (int kk = 0; kk < 4; kk++) {
                int k = kc + k4 * 4 + kk;
                ulonglong2 xa = *(const ulonglong2*)&Xt[k][8 * half];
                ulonglong2 xb = *(const ulonglong2*)&Xt[k][8 * half + 4];
                FMA2(acc[0], xa.x, wp[kk]);
                FMA2(acc[1], xa.y, wp[kk]);
                FMA2(acc[2], xb.x, wp[kk]);
                FMA2(acc[3], xb.y, wp[kk]);
            }
        }
    }
}

// -------- fused (embed +) LN1 + Q/K/V projection: blockIdx.y selects the GEMM --------
// seqs==nullptr (layer 0): rows come from item_emb gather (embed fused).
// y==0: Q = LN1(x) @ Wq^T + bq, writes qin = LN1(x)
// y==1: K = x @ Wk^T + bk + pos_K ; y==2: V = x @ Wv^T + bv + pos_V
__global__ __launch_bounds__(256) void qkv_kernel(
    const float* __restrict__ seqs,
    const int* __restrict__ ids, const float* __restrict__ emb,
    const float* __restrict__ Wq, const float* __restrict__ Wk, const float* __restrict__ Wv,
    const float* __restrict__ bq, const float* __restrict__ bk, const float* __restrict__ bv,
    const float* __restrict__ l1g, const float* __restrict__ l1b,
    const float* __restrict__ posK, const float* __restrict__ posV,
    float* __restrict__ qin,
    float* __restrict__ Yq, float* __restrict__ Yk, float* __restrict__ Yv) {
    __shared__ __align__(16) float Xt[H_][XTS];
    __shared__ __align__(16) float Ws[H_][WPAD];
    __shared__ int ids_sm[GROWS];
    int tid = threadIdx.x;
    int j = tid & 127, half = tid >> 7;
    int row0 = blockIdx.x * GROWS;
    int which = blockIdx.y;

    const float* W      = (which == 0) ? Wq : (which == 1) ? Wk : Wv;
    const float* bias   = (which == 0) ? bq : (which == 1) ? bk : bv;
    const float* addRow = (which == 0) ? nullptr : (which == 1) ? posK : posV;
    float*       Y      = (which == 0) ? Yq : (which == 1) ? Yk : Yv;

    if (seqs == nullptr) {
        // layer 0: gather embedding rows into stage (borrow Ws)
        embed_to_stage(ids, emb, row0, tid, (float*)Ws, ids_sm);
        __syncthreads();
        if (which == 0) {
            ln_stage_inplace(l1g, l1b, qin, row0, tid, (float*)Ws);
            __syncthreads();
        }
        stage_to_xt((const float*)Ws, tid, Xt);
    } else if (which == 0) {
        ln_rows_to_stage(seqs, nullptr, l1g, l1b, qin, row0, tid, (float*)Ws);
        __syncthreads();
        stage_to_xt((const float*)Ws, tid, Xt);
    } else {
        global_to_xt(seqs, row0, tid, Xt);
    }
    // gemm_mainloop's chunk-0 barrier orders the Xt/stage reads before Ws refill

    u64 acc[4];
    gemm_mainloop(W, bias[j], tid, j, half, Xt, Ws, acc);

    #pragma unroll
    for (int p = 0; p < 4; p++) {
        float lo, hi;
        UNPACK2(lo, hi, acc[p]);
        #pragma unroll
        for (int e = 0; e < 2; e++) {
            int r = 8 * half + 2 * p + e;
            int row = row0 + r;
            int l = row % L_;
            float v = e ? hi : lo;
            if (addRow) v += addRow[l * H_ + j];
            Y[row * H_ + j] = v;
        }
    }
}

// -------- fused LN2 + FFN1(relu) + FFN2 + residual + padmask --------
// x = LN2(qin + attn); h = relu(x@W1^T+b1); seqs_out = (x + h@W2^T+b2) * (id!=0)
__global__ __launch_bounds__(256) void ffn_kernel(
    const float* __restrict__ qin, const float* __restrict__ attn,
    const float* __restrict__ l2g, const float* __restrict__ l2b,
    const float* __restrict__ W1, const float* __restrict__ b1,
    const float* __restrict__ W2, const float* __restrict__ b2,
    const int* __restrict__ ids, float* __restrict__ Y) {
    __shared__ __align__(16) float Xt [H_][XTS];   // LN2 output (kept for residual)
    __shared__ __align__(16) float H1t[H_][XTS];   // hidden, transposed
    __shared__ __align__(16) float Ws [H_][WPAD];
    int tid = threadIdx.x;
    int j = tid & 127, half = tid >> 7;
    int row0 = blockIdx.x * GROWS;

    ln_rows_to_stage(qin, attn, l2g, l2b, nullptr, row0, tid, (float*)Ws);
    __syncthreads();
    stage_to_xt((const float*)Ws, tid, Xt);

    u64 acc1[4];
    gemm_mainloop(W1, b1[j], tid, j, half, Xt, Ws, acc1);

    // relu + transpose hidden into H1t (thread owns col j, rows 8*half..+7)
    #pragma unroll
    for (int p = 0; p < 4; p++) {
        float lo, hi;
        UNPACK2(lo, hi, acc1[p]);
        H1t[j][8 * half + 2 * p]     = fmaxf(lo, 0.0f);
        H1t[j][8 * half + 2 * p + 1] = fmaxf(hi, 0.0f);
    }
    __syncthreads();

    u64 acc2[4];
    gemm_mainloop(W2, b2[j], tid, j, half, H1t, Ws, acc2);

    #pragma unroll
    for (int p = 0; p < 4; p++) {
        float lo, hi;
        UNPACK2(lo, hi, acc2[p]);
        #pragma unroll
        for (int e = 0; e < 2; e++) {
            int r = 8 * half + 2 * p + e;
            int row = row0 + r;
            float v = (e ? hi : lo) + Xt[j][r];          // residual: LN2 output
            v = (ids[row] != 0) ? v : 0.0f;              // pad mask
            Y[row * H_ + j] = v;
        }
    }
}

// -------- fused attention, QT=8 queries per block, f32x2-packed --------
__global__ __launch_bounds__(128) void attn_kernel(
    const float* __restrict__ Q, const float* __restrict__ K,
    const float* __restrict__ V, const int* __restrict__ tmat,
    const float* __restrict__ tmK, const float* __restrict__ tmV,
    const int* __restrict__ log_seqs, float* __restrict__ O) {
    int bid = blockIdx.x;
    int qt0 = (bid % (L_ / QT)) * QT;
    int bh  = bid / (L_ / QT);
    int h = bh % NH_;
    int b = bh / NH_;
    int tid = threadIdx.x;

    __shared__ __align__(16) u64   qp_sm[4][HS_];     // packed query pairs
    __shared__ __align__(16) u64   qt2_sm[4][T_];     // packed Qt pairs
    __shared__ __align__(16) float wt2_sm[4][T_][2];  // Wt, parity-interleaved
    __shared__ __align__(16) float p_sm[QT][L_];
    __shared__ unsigned short t_sm[QT][L_];
    __shared__ int padq_sm[QT];
    __shared__ float part_sm[4][QT][HS_];

    if (tid < 4 * HS_) {
        int j = tid >> 5, d = tid & 31;
        const float* q0 = Q + (b * L_ + qt0 + 2 * j) * H_ + h * HS_ + d;
        PACK2(qp_sm[j][d], q0[0], q0[H_]);
    }
    if (tid < QT) padq_sm[tid] = (log_seqs[b * L_ + qt0 + tid] == 0);
    for (int idx = tid; idx < 4 * T_ * 2; idx += 128) ((float*)wt2_sm)[idx] = 0.0f;
    __syncthreads();

    // Qt table: qt2[j][t] = (q_{2j}.tmK[t,h], q_{2j+1}.tmK[t,h])
    for (int t = tid; t < T_; t += 128) {
        const float4* kr = (const float4*)(tmK + t * H_ + h * HS_);
        u64 acc2[4];
        #pragma unroll
        for (int j = 0; j < 4; j++) PACK2(acc2[j], 0.0f, 0.0f);
        #pragma unroll
        for (int d4 = 0; d4 < 8; d4++) {
            float4 kv = kr[d4];
            u64 kp0, kp1, kp2, kp3;
            PACK2(kp0, kv.x, kv.x); PACK2(kp1, kv.y, kv.y);
            PACK2(kp2, kv.z, kv.z); PACK2(kp3, kv.w, kv.w);
            #pragma unroll
            for (int j = 0; j < 4; j++) {
                ulonglong2 qa = *(const ulonglong2*)&qp_sm[j][d4 * 4];
                ulonglong2 qb = *(const ulonglong2*)&qp_sm[j][d4 * 4 + 2];
                FMA2(acc2[j], qa.x, kp0);
                FMA2(acc2[j], qa.y, kp1);
                FMA2(acc2[j], qb.x, kp2);
                FMA2(acc2[j], qb.y, kp3);
            }
        }
        #pragma unroll
        for (int j = 0; j < 4; j++) qt2_sm[j][t] = acc2[j];
    }
    __syncthreads();

    // logits: one key per thread-iteration, all 8 queries packed.
    // tmat gathers prefetched to loop top so their L2 latency overlaps the FMA chain.
    const float* qt2f = (const float*)qt2_sm;
    for (int k = tid; k < L_; k += 128) {
        int trow[QT];
        #pragma unroll
        for (int i = 0; i < QT; i++)
            trow[i] = tmat[(b * L_ + qt0 + i) * L_ + k];

        const float4* kr = (const float4*)(K + (b * L_ + k) * H_ + h * HS_);
        u64 acc2[4];
        #pragma unroll
        for (int j = 0; j < 4; j++) PACK2(acc2[j], 0.0f, 0.0f);
        #pragma unroll
        for (int d4 = 0; d4 < 8; d4++) {
            float4 kv = kr[d4];
            u64 kp0, kp1, kp2, kp3;
            PACK2(kp0, kv.x, kv.x); PACK2(kp1, kv.y, kv.y);
            PACK2(kp2, kv.z, kv.z); PACK2(kp3, kv.w, kv.w);
            #pragma unroll
            for (int j = 0; j < 4; j++) {
                ulonglong2 qa = *(const ulonglong2*)&qp_sm[j][d4 * 4];
                ulonglong2 qb = *(const ulonglong2*)&qp_sm[j][d4 * 4 + 2];
                FMA2(acc2[j], qa.x, kp0);
                FMA2(acc2[j], qa.y, kp1);
                FMA2(acc2[j], qb.x, kp2);
                FMA2(acc2[j], qb.y, kp3);
            }
        }
        #pragma unroll
        for (int j = 0; j < 4; j++) {
            float lo, hi;
            UNPACK2(lo, hi, acc2[j]);
            #pragma unroll
            for (int e = 0; e < 2; e++) {
                int i = 2 * j + e;
                int t = trow[i];
                t_sm[i][k] = (unsigned short)t;
                float a = ((e ? hi : lo) + qt2f[(j * T_ + t) * 2 + e]) * SCALE;
                if (k > qt0 + i || padq_sm[i]) a = NEGF;
                p_sm[i][k] = a;
            }
        }
    }
    __syncthreads();

    // warp-local softmax (warp w owns rows 2w, 2w+1) + time-bucket scatter
    {
        int w = tid >> 5, lane = tid & 31;
        #pragma unroll
        for (int ii = 0; ii < 2; ii++) {
            int i = 2 * w + ii;
            float m = -INFINITY;
            for (int k = lane; k < L_; k += 32) m = fmaxf(m, p_sm[i][k]);
            #pragma unroll
            for (int o = 16; o; o >>= 1) m = fmaxf(m, __shfl_xor_sync(0xffffffffu, m, o));
            float s = 0.0f;
            for (int k = lane; k < L_; k += 32) {
                float e = __expf(p_sm[i][k] - m);
                p_sm[i][k] = e;
                s += e;
            }
            #pragma unroll
            for (int o = 16; o; o >>= 1) s += __shfl_xor_sync(0xffffffffu, s, o);
            float inv = 1.0f / s;
            for (int k = lane; k < L_; k += 32) {
                float pv = p_sm[i][k] * inv;
                p_sm[i][k] = pv;
                atomicAdd(&wt2_sm[i >> 1][t_sm[i][k]][i & 1], pv);
            }
        }
    }
    __syncthreads();

    // output: content term packed over KEY pairs, time term packed over QUERY pairs
    {
        int part = tid >> 5, d = tid & 31;
        u64 acck2[QT];
        u64 accq2[4];
        #pragma unroll
        for (int i = 0; i < QT; i++) PACK2(acck2[i], 0.0f, 0.0f);
        #pragma unroll
        for (int j = 0; j < 4; j++) PACK2(accq2[j], 0.0f, 0.0f);

        for (int kp = part; kp < L_ / 2; kp += 4) {
            int k = 2 * kp;
            const float* vb = V + (b * L_ + k) * H_ + h * HS_ + d;
            u64 vp;
            PACK2(vp, vb[0], vb[H_]);
            #pragma unroll
            for (int i = 0; i < QT; i++) {
                u64 pp = *(const u64*)&p_sm[i][k];
                FMA2(acck2[i], pp, vp);
            }
        }
        for (int t = part; t < T_; t += 4) {
            float tv = tmV[t * H_ + h * HS_ + d];
            u64 tp;
            PACK2(tp, tv, tv);
            #pragma unroll
            for (int j = 0; j < 4; j++) {
                u64 wtp = *(const u64*)&wt2_sm[j][t][0];
                FMA2(accq2[j], wtp, tp);
            }
        }
        #pragma unroll
        for (int i = 0; i < QT; i++) {
            float l0, h0, ql, qh;
            UNPACK2(l0, h0, acck2[i]);
            UNPACK2(ql, qh, accq2[i >> 1]);
            part_sm[part][i][d] = l0 + h0 + ((i & 1) ? qh : ql);
        }
    }
    __syncthreads();
    for (int idx = tid; idx < QT * HS_; idx += 128) {
        int i = idx >> 5, d = idx & 31;
        float o = part_sm[0][i][d] + part_sm[1][i][d] + part_sm[2][i][d] + part_sm[3][i][d];
        O[(b * L_ + qt0 + i) * H_ + h * HS_ + d] = o;
    }
}

// -------- fused final LN + pos/neg logits --------
__global__ void ln_logits_kernel(const float* __restrict__ X,
                                 const float* __restrict__ g, const float* __restrict__ b,
                                 const float* __restrict__ emb,
                                 const int* __restrict__ pos, const int* __restrict__ neg,
                                 float* __restrict__ out) {
    int row = blockIdx.x, tid = threadIdx.x;
    float x = X[row * H_ + tid];
    float s = x, s2 = x * x;
    #pragma unroll
    for (int o = 16; o; o >>= 1) {
        s  += __shfl_xor_sync(0xffffffffu, s,  o);
        s2 += __shfl_xor_sync(0xffffffffu, s2, o);
    }
    __shared__ float sm[8];
    if ((tid & 31) == 0) { sm[tid >> 5] = s; sm[4 + (tid >> 5)] = s2; }
    __syncthreads();
    float mean = (sm[0] + sm[1] + sm[2] + sm[3]) * (1.0f / H_);
    float ex2  = (sm[4] + sm[5] + sm[6] + sm[7]) * (1.0f / H_);
    float var  = ex2 - mean * mean;
    float f = (x - mean) * rsqrtf(var + 1e-8f) * g[tid] + b[tid];

    float p = f * emb[pos[row] * H_ + tid];
    float n = f * emb[neg[row] * H_ + tid];
    #pragma unroll
    for (int o = 16; o; o >>= 1) {
        p += __shfl_xor_sync(0xffffffffu, p, o);
        n += __shfl_xor_sync(0xffffffffu, n, o);
    }
    __shared__ float sp[4], sn[4];
    if ((tid & 31) == 0) { sp[tid >> 5] = p; sn[tid >> 5] = n; }
    __syncthreads();
    if (tid == 0) {
        out[row]       = sp[0] + sp[1] + sp[2] + sp[3];
        out[BT_ + row] = sn[0] + sn[1] + sn[2] + sn[3];
    }
}

extern "C" void kernel_launch(void* const* d_in, const int* in_sizes, int n_in,
                              void* d_out, int out_size) {
    const int*   log_seqs = (const int*)  d_in[0];
    const int*   tmat     = (const int*)  d_in[1];
    const int*   pos_seqs = (const int*)  d_in[2];
    const int*   neg_seqs = (const int*)  d_in[3];
    // d_in[4] = user_ids (unused by reference)
    const float* item_emb = (const float*)d_in[5];
    const float* pos_K    = (const float*)d_in[6];
    const float* pos_V    = (const float*)d_in[7];
    const float* tm_K     = (const float*)d_in[8];
    const float* tm_V     = (const float*)d_in[9];
    const float* Wq  = (const float*)d_in[10]; const float* bq  = (const float*)d_in[11];
    const float* Wk  = (const float*)d_in[12]; const float* bk  = (const float*)d_in[13];
    const float* Wv  = (const float*)d_in[14]; const float* bv  = (const float*)d_in[15];
    const float* l1g = (const float*)d_in[16]; const float* l1b = (const float*)d_in[17];
    const float* l2g = (const float*)d_in[18]; const float* l2b = (const float*)d_in[19];
    const float* W1  = (const float*)d_in[20]; const float* b1  = (const float*)d_in[21];
    const float* W2  = (const float*)d_in[22]; const float* b2  = (const float*)d_in[23];
    const float* lfg = (const float*)d_in[24]; const float* lfb = (const float*)d_in[25];
    float* out = (float*)d_out;

    float *seqs, *qin, *q, *k, *v, *attn;
    cudaGetSymbolAddress((void**)&seqs, g_seqs);
    cudaGetSymbolAddress((void**)&qin,  g_qin);
    cudaGetSymbolAddress((void**)&q,    g_q);
    cudaGetSymbolAddress((void**)&k,    g_k);
    cudaGetSymbolAddress((void**)&v,    g_v);
    cudaGetSymbolAddress((void**)&attn, g_attn);

    for (int i = 0; i < 2; i++) {
        const int WO = i * H_ * H_, BO = i * H_;
        const float* src = (i == 0) ? nullptr : seqs;   // layer 0: embed fused in qkv
        qkv_kernel<<<dim3(BT_ / GROWS, 3), 256>>>(
            src, log_seqs, item_emb,
            Wq + WO, Wk + WO, Wv + WO, bq + BO, bk + BO, bv + BO,
            l1g + BO, l1b + BO, pos_K, pos_V, qin, q, k, v);
        attn_kernel<<<B_ * NH_ * (L_ / QT), 128>>>(q, k, v, tmat, tm_K, tm_V, log_seqs, attn);
        ffn_kernel<<<BT_ / GROWS, 256>>>(
            qin, attn, l2g + BO, l2b + BO, W1 + WO, b1 + BO, W2 + WO, b2 + BO,
            log_seqs, seqs);
    }

    ln_logits_kernel<<<BT_, 128>>>(seqs, lfg, lfb, item_emb, pos_seqs, neg_seqs, out);
}